// round 5
// baseline (speedup 1.0000x reference)
#include <cuda_runtime.h>
#include <cstdint>

// ---------------------------------------------------------------------------
// DistributedMPNN: 3 message-passing rounds (shared weights) + h2o head.
//
//   P[n][32]   = x[n](9) @ Wm1[0:9] + bm1                (per-node hoist of edge layer-1)
//   per edge:  m1 = relu(P[src] + ea*Wm1[9])             (32 FMA)
//              m2 = relu(m1 @ Wm2 + bm2)                 (32x32, fma.rn.f32x2)
//              aggr[dst] += m2                           (red.global.add.v4.f32)
//   per node:  u1 = relu([x,aggr] @ Wu1 + bu1)  (41x16)
//              u2 = relu(u1 @ Wu2 + bu2)        (16x8)
//              x  = [x0, u2];  P = x @ Wm1x + bm1;  aggr = 0
//   final:     o = relu(u2 @ Wh1 + bh1); out = sigmoid(o @ Wh2 + bh2)
// ---------------------------------------------------------------------------

#define MAXN 50000
#define MAXE 1600000

__device__ float g_P[MAXN * 32];     // per-node layer-1 pre-activation (incl. bm1)
__device__ float g_aggr[MAXN * 32];  // scatter-sum accumulator
__device__ float g_x[MAXN * 9];      // current node features
__device__ int   g_is64;             // edge_index dtype flag

// ---------------------------------------------------------------------------
// Detect edge_index dtype. If int64 (little-endian, values in [0,50000)),
// every odd 32-bit word is 0. For int32 data, 256 consecutive odd-position
// index values being all zero is impossible (p ~ (2e-5)^256).
// ---------------------------------------------------------------------------
__global__ void detect_kernel(const int* __restrict__ w) {
    __shared__ int nz;
    if (threadIdx.x == 0) nz = 0;
    __syncthreads();
    if (w[2 * threadIdx.x + 1] != 0) atomicOr(&nz, 1);
    __syncthreads();
    if (threadIdx.x == 0) g_is64 = (nz == 0) ? 1 : 0;
}

// ---------------------------------------------------------------------------
// Init: copy x -> g_x, compute P, zero aggr. One thread per (node, j).
// ---------------------------------------------------------------------------
__global__ void init_kernel(const float* __restrict__ x,
                            const float* __restrict__ Wm1,
                            const float* __restrict__ bm1, int N) {
    int idx = blockIdx.x * blockDim.x + threadIdx.x;
    int n = idx >> 5;
    int j = idx & 31;
    if (n >= N) return;
    float s = bm1[j];
#pragma unroll
    for (int c = 0; c < 9; c++) s = fmaf(x[n * 9 + c], Wm1[c * 32 + j], s);
    g_P[idx] = s;
    g_aggr[idx] = 0.f;
    if (j < 9) g_x[n * 9 + j] = x[n * 9 + j];
}

// ---------------------------------------------------------------------------
// Edge kernel: one thread per edge. Layer-2 with packed f32x2 FMA, weights in
// shared (broadcast LDS.128). Scatter-sum via red.global.add.v4.f32.
// ---------------------------------------------------------------------------
__global__ void __launch_bounds__(256, 2)
edge_kernel(const void* __restrict__ eiv, const float* __restrict__ ea,
            const float* __restrict__ Wm1, const float* __restrict__ bm2,
            const float* __restrict__ Wm2, int E) {
    __shared__ __align__(16) float sW2[1024];  // Wm2 [32][32] row-major
    __shared__ __align__(16) float sW9[32];    // Wm1 row 9 (edge_attr weights)
    __shared__ __align__(16) float sB2[32];    // bm2

    for (int i = threadIdx.x; i < 1024; i += 256) sW2[i] = Wm2[i];
    if (threadIdx.x < 32) {
        sW9[threadIdx.x] = Wm1[9 * 32 + threadIdx.x];
        sB2[threadIdx.x] = bm2[threadIdx.x];
    }
    __syncthreads();

    int e = blockIdx.x * 256 + threadIdx.x;
    if (e >= E) return;

    int src, dst;
    if (g_is64) {
        const long long* ei = (const long long*)eiv;
        src = (int)ei[e];
        dst = (int)ei[(size_t)E + e];
    } else {
        const int* ei = (const int*)eiv;
        src = ei[e];
        dst = ei[(size_t)E + e];
    }
    float a = ea[e];

    // m1 = relu(P[src] + a * W9)   (bm1 already folded into P)
    const float4* Pr = (const float4*)(g_P + (size_t)src * 32);
    float m1[32];
#pragma unroll
    for (int q = 0; q < 8; q++) {
        float4 p = Pr[q];
        m1[4 * q + 0] = fmaxf(fmaf(a, sW9[4 * q + 0], p.x), 0.f);
        m1[4 * q + 1] = fmaxf(fmaf(a, sW9[4 * q + 1], p.y), 0.f);
        m1[4 * q + 2] = fmaxf(fmaf(a, sW9[4 * q + 2], p.z), 0.f);
        m1[4 * q + 3] = fmaxf(fmaf(a, sW9[4 * q + 3], p.w), 0.f);
    }

    // layer 2: acc[j] = bm2[j] + sum_k m1[k] * Wm2[k][j], packed over j-pairs
    unsigned long long acc[16];
    const unsigned long long* b2 = (const unsigned long long*)sB2;
#pragma unroll
    for (int q = 0; q < 16; q++) acc[q] = b2[q];

#pragma unroll
    for (int k = 0; k < 32; k++) {
        unsigned long long mk2;
        asm("mov.b64 %0, {%1, %1};" : "=l"(mk2) : "r"(__float_as_uint(m1[k])));
        const ulonglong2* wr = (const ulonglong2*)(sW2 + k * 32);
#pragma unroll
        for (int q = 0; q < 8; q++) {
            ulonglong2 w = wr[q];  // LDS.128, warp-uniform broadcast
            asm("fma.rn.f32x2 %0, %1, %2, %0;"
                : "+l"(acc[2 * q]) : "l"(mk2), "l"(w.x));
            asm("fma.rn.f32x2 %0, %1, %2, %0;"
                : "+l"(acc[2 * q + 1]) : "l"(mk2), "l"(w.y));
        }
    }

    // relu + vectorized scatter-add
    size_t gaddr = __cvta_generic_to_global((void*)(g_aggr + (size_t)dst * 32));
#pragma unroll
    for (int q = 0; q < 8; q++) {
        unsigned r0, r1, r2, r3;
        asm("mov.b64 {%0, %1}, %2;" : "=r"(r0), "=r"(r1) : "l"(acc[2 * q]));
        asm("mov.b64 {%0, %1}, %2;" : "=r"(r2), "=r"(r3) : "l"(acc[2 * q + 1]));
        float v0 = fmaxf(__uint_as_float(r0), 0.f);
        float v1 = fmaxf(__uint_as_float(r1), 0.f);
        float v2 = fmaxf(__uint_as_float(r2), 0.f);
        float v3 = fmaxf(__uint_as_float(r3), 0.f);
        asm volatile("red.global.add.v4.f32 [%0], {%1, %2, %3, %4};"
                     :: "l"((unsigned long long)(gaddr + q * 16)),
                        "f"(v0), "f"(v1), "f"(v2), "f"(v3)
                     : "memory");
    }
}

// ---------------------------------------------------------------------------
// Node update (rounds 0,1): u1/u2 MLP, writes new x, next P, zeroes aggr.
// One thread per node, weights staged in shared.
// ---------------------------------------------------------------------------
__global__ void __launch_bounds__(128, 4)
update_kernel(const float* __restrict__ Wu1, const float* __restrict__ bu1,
              const float* __restrict__ Wu2, const float* __restrict__ bu2,
              const float* __restrict__ Wm1, const float* __restrict__ bm1,
              int N) {
    __shared__ float sWu1[656], sWu2[128], sWm1[288];
    __shared__ float sbu1[16], sbu2[8], sbm1[32];
    for (int i = threadIdx.x; i < 656; i += blockDim.x) sWu1[i] = Wu1[i];
    for (int i = threadIdx.x; i < 128; i += blockDim.x) sWu2[i] = Wu2[i];
    for (int i = threadIdx.x; i < 288; i += blockDim.x) sWm1[i] = Wm1[i];
    if (threadIdx.x < 16) sbu1[threadIdx.x] = bu1[threadIdx.x];
    if (threadIdx.x < 8)  sbu2[threadIdx.x] = bu2[threadIdx.x];
    if (threadIdx.x < 32) sbm1[threadIdx.x] = bm1[threadIdx.x];
    __syncthreads();

    int n = blockIdx.x * blockDim.x + threadIdx.x;
    if (n >= N) return;

    float xv[9];
#pragma unroll
    for (int c = 0; c < 9; c++) xv[c] = g_x[n * 9 + c];

    float ag[32];
    float4* ar = (float4*)(g_aggr + (size_t)n * 32);
#pragma unroll
    for (int q = 0; q < 8; q++) {
        float4 t = ar[q];
        ag[4 * q + 0] = t.x; ag[4 * q + 1] = t.y;
        ag[4 * q + 2] = t.z; ag[4 * q + 3] = t.w;
    }

    float u1[16];
#pragma unroll
    for (int i = 0; i < 16; i++) u1[i] = sbu1[i];
#pragma unroll
    for (int c = 0; c < 9; c++) {
        float xc = xv[c];
#pragma unroll
        for (int i = 0; i < 16; i++) u1[i] = fmaf(xc, sWu1[c * 16 + i], u1[i]);
    }
#pragma unroll
    for (int k = 0; k < 32; k++) {
        float gk = ag[k];
#pragma unroll
        for (int i = 0; i < 16; i++) u1[i] = fmaf(gk, sWu1[(9 + k) * 16 + i], u1[i]);
    }
#pragma unroll
    for (int i = 0; i < 16; i++) u1[i] = fmaxf(u1[i], 0.f);

    float u2[8];
#pragma unroll
    for (int j = 0; j < 8; j++) u2[j] = sbu2[j];
#pragma unroll
    for (int i = 0; i < 16; i++) {
        float ui = u1[i];
#pragma unroll
        for (int j = 0; j < 8; j++) u2[j] = fmaf(ui, sWu2[i * 8 + j], u2[j]);
    }
#pragma unroll
    for (int j = 0; j < 8; j++) u2[j] = fmaxf(u2[j], 0.f);

    float nx[9];
    nx[0] = xv[0];
#pragma unroll
    for (int j = 0; j < 8; j++) nx[1 + j] = u2[j];
#pragma unroll
    for (int c = 0; c < 9; c++) g_x[n * 9 + c] = nx[c];

    // next-round P and zero aggr
    float p[32];
#pragma unroll
    for (int j = 0; j < 32; j++) p[j] = sbm1[j];
#pragma unroll
    for (int c = 0; c < 9; c++) {
        float xc = nx[c];
#pragma unroll
        for (int j = 0; j < 32; j++) p[j] = fmaf(xc, sWm1[c * 32 + j], p[j]);
    }
    float4* Pr = (float4*)(g_P + (size_t)n * 32);
    float4 z4 = make_float4(0.f, 0.f, 0.f, 0.f);
#pragma unroll
    for (int q = 0; q < 8; q++) {
        Pr[q] = make_float4(p[4 * q], p[4 * q + 1], p[4 * q + 2], p[4 * q + 3]);
        ar[q] = z4;
    }
}

// ---------------------------------------------------------------------------
// Final round: update MLP fused with h2o head. Writes sigmoid output.
// ---------------------------------------------------------------------------
__global__ void __launch_bounds__(128, 4)
final_kernel(const float* __restrict__ Wu1, const float* __restrict__ bu1,
             const float* __restrict__ Wu2, const float* __restrict__ bu2,
             const float* __restrict__ Wh1, const float* __restrict__ bh1,
             const float* __restrict__ Wh2, const float* __restrict__ bh2,
             float* __restrict__ out, int N) {
    __shared__ float sWu1[656], sWu2[128], sWh1[128], sWh2[16];
    __shared__ float sbu1[16], sbu2[8], sbh1[16], sbh2;
    for (int i = threadIdx.x; i < 656; i += blockDim.x) sWu1[i] = Wu1[i];
    for (int i = threadIdx.x; i < 128; i += blockDim.x) sWu2[i] = Wu2[i];
    for (int i = threadIdx.x; i < 128; i += blockDim.x) sWh1[i] = Wh1[i];
    if (threadIdx.x < 16) { sWh2[threadIdx.x] = Wh2[threadIdx.x]; sbu1[threadIdx.x] = bu1[threadIdx.x]; sbh1[threadIdx.x] = bh1[threadIdx.x]; }
    if (threadIdx.x < 8)  sbu2[threadIdx.x] = bu2[threadIdx.x];
    if (threadIdx.x == 0) sbh2 = bh2[0];
    __syncthreads();

    int n = blockIdx.x * blockDim.x + threadIdx.x;
    if (n >= N) return;

    float xv[9];
#pragma unroll
    for (int c = 0; c < 9; c++) xv[c] = g_x[n * 9 + c];

    float ag[32];
    const float4* ar = (const float4*)(g_aggr + (size_t)n * 32);
#pragma unroll
    for (int q = 0; q < 8; q++) {
        float4 t = ar[q];
        ag[4 * q + 0] = t.x; ag[4 * q + 1] = t.y;
        ag[4 * q + 2] = t.z; ag[4 * q + 3] = t.w;
    }

    float u1[16];
#pragma unroll
    for (int i = 0; i < 16; i++) u1[i] = sbu1[i];
#pragma unroll
    for (int c = 0; c < 9; c++) {
        float xc = xv[c];
#pragma unroll
        for (int i = 0; i < 16; i++) u1[i] = fmaf(xc, sWu1[c * 16 + i], u1[i]);
    }
#pragma unroll
    for (int k = 0; k < 32; k++) {
        float gk = ag[k];
#pragma unroll
        for (int i = 0; i < 16; i++) u1[i] = fmaf(gk, sWu1[(9 + k) * 16 + i], u1[i]);
    }
#pragma unroll
    for (int i = 0; i < 16; i++) u1[i] = fmaxf(u1[i], 0.f);

    float u2[8];
#pragma unroll
    for (int j = 0; j < 8; j++) u2[j] = sbu2[j];
#pragma unroll
    for (int i = 0; i < 16; i++) {
        float ui = u1[i];
#pragma unroll
        for (int j = 0; j < 8; j++) u2[j] = fmaf(ui, sWu2[i * 8 + j], u2[j]);
    }
#pragma unroll
    for (int j = 0; j < 8; j++) u2[j] = fmaxf(u2[j], 0.f);

    // h2o: o = relu(u2 @ Wh1 + bh1); z = o . Wh2 + bh2
    float o[16];
#pragma unroll
    for (int i = 0; i < 16; i++) o[i] = sbh1[i];
#pragma unroll
    for (int c = 0; c < 8; c++) {
        float uc = u2[c];
#pragma unroll
        for (int i = 0; i < 16; i++) o[i] = fmaf(uc, sWh1[c * 16 + i], o[i]);
    }
    float z = sbh2;
#pragma unroll
    for (int i = 0; i < 16; i++) z = fmaf(fmaxf(o[i], 0.f), sWh2[i], z);

    out[n] = 1.f / (1.f + __expf(-z));
}

// ---------------------------------------------------------------------------
extern "C" void kernel_launch(void* const* d_in, const int* in_sizes, int n_in,
                              void* d_out, int out_size) {
    const float* x   = (const float*)d_in[0];
    const void*  ei  = d_in[1];
    const float* ea  = (const float*)d_in[2];
    const float* Wm1 = (const float*)d_in[3];
    const float* bm1 = (const float*)d_in[4];
    const float* Wm2 = (const float*)d_in[5];
    const float* bm2 = (const float*)d_in[6];
    const float* Wu1 = (const float*)d_in[7];
    const float* bu1 = (const float*)d_in[8];
    const float* Wu2 = (const float*)d_in[9];
    const float* bu2 = (const float*)d_in[10];
    const float* Wh1 = (const float*)d_in[11];
    const float* bh1 = (const float*)d_in[12];
    const float* Wh2 = (const float*)d_in[13];
    const float* bh2 = (const float*)d_in[14];
    float* out = (float*)d_out;

    int N = in_sizes[0] / 9;
    int E = in_sizes[2];  // edge_attr is [E, 1]

    detect_kernel<<<1, 256>>>((const int*)ei);
    init_kernel<<<(N * 32 + 255) / 256, 256>>>(x, Wm1, bm1, N);
    for (int r = 0; r < 3; r++) {
        edge_kernel<<<(E + 255) / 256, 256>>>(ei, ea, Wm1, bm2, Wm2, E);
        if (r < 2)
            update_kernel<<<(N + 127) / 128, 128>>>(Wu1, bu1, Wu2, bu2, Wm1, bm1, N);
        else
            final_kernel<<<(N + 127) / 128, 128>>>(Wu1, bu1, Wu2, bu2,
                                                   Wh1, bh1, Wh2, bh2, out, N);
    }
}

// round 6
// speedup vs baseline: 1.0010x; 1.0010x over previous
#include <cuda_runtime.h>
#include <cstdint>

// ---------------------------------------------------------------------------
// DistributedMPNN: 3 message-passing rounds (shared weights) + h2o head.
//
//   P[n][32]   = x[n](9) @ Wm1[0:9] + bm1                (per-node hoist of edge layer-1)
//   per edge:  m1 = relu(P[src] + ea*Wm1[9])             (32 FMA)
//              m2 = relu(m1 @ Wm2 + bm2)                 (32x32, fma.rn.f32x2)
//              aggr[dst] += m2                           (red.global.add.v4.f32)
//   per node:  u1 = relu([x,aggr] @ Wu1 + bu1)  (41x16)
//              u2 = relu(u1 @ Wu2 + bu2)        (16x8)
//              x  = [x0, u2];  P = x @ Wm1x + bm1;  aggr = 0
//   final:     o = relu(u2 @ Wh1 + bh1); out = sigmoid(o @ Wh2 + bh2)
// ---------------------------------------------------------------------------

#define MAXN 50000
#define MAXE 1600000

__device__ float g_P[MAXN * 32];     // per-node layer-1 pre-activation (incl. bm1)
__device__ float g_aggr[MAXN * 32];  // scatter-sum accumulator
__device__ float g_x[MAXN * 9];      // current node features
__device__ int   g_is64;             // edge_index dtype flag

// ---------------------------------------------------------------------------
// Detect edge_index dtype. If int64 (little-endian, values in [0,50000)),
// every odd 32-bit word is 0. For int32 data, 256 consecutive odd-position
// index values being all zero is impossible (p ~ (2e-5)^256).
// ---------------------------------------------------------------------------
__global__ void detect_kernel(const int* __restrict__ w) {
    __shared__ int nz;
    if (threadIdx.x == 0) nz = 0;
    __syncthreads();
    if (w[2 * threadIdx.x + 1] != 0) atomicOr(&nz, 1);
    __syncthreads();
    if (threadIdx.x == 0) g_is64 = (nz == 0) ? 1 : 0;
}

// ---------------------------------------------------------------------------
// Init: copy x -> g_x, compute P, zero aggr. One thread per (node, j).
// ---------------------------------------------------------------------------
__global__ void init_kernel(const float* __restrict__ x,
                            const float* __restrict__ Wm1,
                            const float* __restrict__ bm1, int N) {
    int idx = blockIdx.x * blockDim.x + threadIdx.x;
    int n = idx >> 5;
    int j = idx & 31;
    if (n >= N) return;
    float s = bm1[j];
#pragma unroll
    for (int c = 0; c < 9; c++) s = fmaf(x[n * 9 + c], Wm1[c * 32 + j], s);
    g_P[idx] = s;
    g_aggr[idx] = 0.f;
    if (j < 9) g_x[n * 9 + j] = x[n * 9 + j];
}

// ---------------------------------------------------------------------------
// Edge kernel: one thread per edge. Layer-2 with packed f32x2 FMA, weights in
// shared (broadcast LDS.128). Scatter-sum via red.global.add.v4.f32.
// ---------------------------------------------------------------------------
__global__ void __launch_bounds__(256, 2)
edge_kernel(const void* __restrict__ eiv, const float* __restrict__ ea,
            const float* __restrict__ Wm1, const float* __restrict__ bm2,
            const float* __restrict__ Wm2, int E) {
    __shared__ __align__(16) float sW2[1024];  // Wm2 [32][32] row-major
    __shared__ __align__(16) float sW9[32];    // Wm1 row 9 (edge_attr weights)
    __shared__ __align__(16) float sB2[32];    // bm2

    for (int i = threadIdx.x; i < 1024; i += 256) sW2[i] = Wm2[i];
    if (threadIdx.x < 32) {
        sW9[threadIdx.x] = Wm1[9 * 32 + threadIdx.x];
        sB2[threadIdx.x] = bm2[threadIdx.x];
    }
    __syncthreads();

    int e = blockIdx.x * 256 + threadIdx.x;
    if (e >= E) return;

    int src, dst;
    if (g_is64) {
        const long long* ei = (const long long*)eiv;
        src = (int)ei[e];
        dst = (int)ei[(size_t)E + e];
    } else {
        const int* ei = (const int*)eiv;
        src = ei[e];
        dst = ei[(size_t)E + e];
    }
    float a = ea[e];

    // m1 = relu(P[src] + a * W9)   (bm1 already folded into P)
    const float4* Pr = (const float4*)(g_P + (size_t)src * 32);
    float m1[32];
#pragma unroll
    for (int q = 0; q < 8; q++) {
        float4 p = Pr[q];
        m1[4 * q + 0] = fmaxf(fmaf(a, sW9[4 * q + 0], p.x), 0.f);
        m1[4 * q + 1] = fmaxf(fmaf(a, sW9[4 * q + 1], p.y), 0.f);
        m1[4 * q + 2] = fmaxf(fmaf(a, sW9[4 * q + 2], p.z), 0.f);
        m1[4 * q + 3] = fmaxf(fmaf(a, sW9[4 * q + 3], p.w), 0.f);
    }

    // layer 2: acc[j] = bm2[j] + sum_k m1[k] * Wm2[k][j], packed over j-pairs
    unsigned long long acc[16];
    const unsigned long long* b2 = (const unsigned long long*)sB2;
#pragma unroll
    for (int q = 0; q < 16; q++) acc[q] = b2[q];

#pragma unroll
    for (int k = 0; k < 32; k++) {
        unsigned long long mk2;
        asm("mov.b64 %0, {%1, %1};" : "=l"(mk2) : "r"(__float_as_uint(m1[k])));
        const ulonglong2* wr = (const ulonglong2*)(sW2 + k * 32);
#pragma unroll
        for (int q = 0; q < 8; q++) {
            ulonglong2 w = wr[q];  // LDS.128, warp-uniform broadcast
            asm("fma.rn.f32x2 %0, %1, %2, %0;"
                : "+l"(acc[2 * q]) : "l"(mk2), "l"(w.x));
            asm("fma.rn.f32x2 %0, %1, %2, %0;"
                : "+l"(acc[2 * q + 1]) : "l"(mk2), "l"(w.y));
        }
    }

    // relu + vectorized scatter-add
    size_t gaddr = __cvta_generic_to_global((void*)(g_aggr + (size_t)dst * 32));
#pragma unroll
    for (int q = 0; q < 8; q++) {
        unsigned r0, r1, r2, r3;
        asm("mov.b64 {%0, %1}, %2;" : "=r"(r0), "=r"(r1) : "l"(acc[2 * q]));
        asm("mov.b64 {%0, %1}, %2;" : "=r"(r2), "=r"(r3) : "l"(acc[2 * q + 1]));
        float v0 = fmaxf(__uint_as_float(r0), 0.f);
        float v1 = fmaxf(__uint_as_float(r1), 0.f);
        float v2 = fmaxf(__uint_as_float(r2), 0.f);
        float v3 = fmaxf(__uint_as_float(r3), 0.f);
        asm volatile("red.global.add.v4.f32 [%0], {%1, %2, %3, %4};"
                     :: "l"((unsigned long long)(gaddr + q * 16)),
                        "f"(v0), "f"(v1), "f"(v2), "f"(v3)
                     : "memory");
    }
}

// ---------------------------------------------------------------------------
// Node update (rounds 0,1): u1/u2 MLP, writes new x, next P, zeroes aggr.
// One thread per node, weights staged in shared.
// ---------------------------------------------------------------------------
__global__ void __launch_bounds__(128, 4)
update_kernel(const float* __restrict__ Wu1, const float* __restrict__ bu1,
              const float* __restrict__ Wu2, const float* __restrict__ bu2,
              const float* __restrict__ Wm1, const float* __restrict__ bm1,
              int N) {
    __shared__ float sWu1[656], sWu2[128], sWm1[288];
    __shared__ float sbu1[16], sbu2[8], sbm1[32];
    for (int i = threadIdx.x; i < 656; i += blockDim.x) sWu1[i] = Wu1[i];
    for (int i = threadIdx.x; i < 128; i += blockDim.x) sWu2[i] = Wu2[i];
    for (int i = threadIdx.x; i < 288; i += blockDim.x) sWm1[i] = Wm1[i];
    if (threadIdx.x < 16) sbu1[threadIdx.x] = bu1[threadIdx.x];
    if (threadIdx.x < 8)  sbu2[threadIdx.x] = bu2[threadIdx.x];
    if (threadIdx.x < 32) sbm1[threadIdx.x] = bm1[threadIdx.x];
    __syncthreads();

    int n = blockIdx.x * blockDim.x + threadIdx.x;
    if (n >= N) return;

    float xv[9];
#pragma unroll
    for (int c = 0; c < 9; c++) xv[c] = g_x[n * 9 + c];

    float ag[32];
    float4* ar = (float4*)(g_aggr + (size_t)n * 32);
#pragma unroll
    for (int q = 0; q < 8; q++) {
        float4 t = ar[q];
        ag[4 * q + 0] = t.x; ag[4 * q + 1] = t.y;
        ag[4 * q + 2] = t.z; ag[4 * q + 3] = t.w;
    }

    float u1[16];
#pragma unroll
    for (int i = 0; i < 16; i++) u1[i] = sbu1[i];
#pragma unroll
    for (int c = 0; c < 9; c++) {
        float xc = xv[c];
#pragma unroll
        for (int i = 0; i < 16; i++) u1[i] = fmaf(xc, sWu1[c * 16 + i], u1[i]);
    }
#pragma unroll
    for (int k = 0; k < 32; k++) {
        float gk = ag[k];
#pragma unroll
        for (int i = 0; i < 16; i++) u1[i] = fmaf(gk, sWu1[(9 + k) * 16 + i], u1[i]);
    }
#pragma unroll
    for (int i = 0; i < 16; i++) u1[i] = fmaxf(u1[i], 0.f);

    float u2[8];
#pragma unroll
    for (int j = 0; j < 8; j++) u2[j] = sbu2[j];
#pragma unroll
    for (int i = 0; i < 16; i++) {
        float ui = u1[i];
#pragma unroll
        for (int j = 0; j < 8; j++) u2[j] = fmaf(ui, sWu2[i * 8 + j], u2[j]);
    }
#pragma unroll
    for (int j = 0; j < 8; j++) u2[j] = fmaxf(u2[j], 0.f);

    float nx[9];
    nx[0] = xv[0];
#pragma unroll
    for (int j = 0; j < 8; j++) nx[1 + j] = u2[j];
#pragma unroll
    for (int c = 0; c < 9; c++) g_x[n * 9 + c] = nx[c];

    // next-round P and zero aggr
    float p[32];
#pragma unroll
    for (int j = 0; j < 32; j++) p[j] = sbm1[j];
#pragma unroll
    for (int c = 0; c < 9; c++) {
        float xc = nx[c];
#pragma unroll
        for (int j = 0; j < 32; j++) p[j] = fmaf(xc, sWm1[c * 32 + j], p[j]);
    }
    float4* Pr = (float4*)(g_P + (size_t)n * 32);
    float4 z4 = make_float4(0.f, 0.f, 0.f, 0.f);
#pragma unroll
    for (int q = 0; q < 8; q++) {
        Pr[q] = make_float4(p[4 * q], p[4 * q + 1], p[4 * q + 2], p[4 * q + 3]);
        ar[q] = z4;
    }
}

// ---------------------------------------------------------------------------
// Final round: update MLP fused with h2o head. Writes sigmoid output.
// ---------------------------------------------------------------------------
__global__ void __launch_bounds__(128, 4)
final_kernel(const float* __restrict__ Wu1, const float* __restrict__ bu1,
             const float* __restrict__ Wu2, const float* __restrict__ bu2,
             const float* __restrict__ Wh1, const float* __restrict__ bh1,
             const float* __restrict__ Wh2, const float* __restrict__ bh2,
             float* __restrict__ out, int N) {
    __shared__ float sWu1[656], sWu2[128], sWh1[128], sWh2[16];
    __shared__ float sbu1[16], sbu2[8], sbh1[16], sbh2;
    for (int i = threadIdx.x; i < 656; i += blockDim.x) sWu1[i] = Wu1[i];
    for (int i = threadIdx.x; i < 128; i += blockDim.x) sWu2[i] = Wu2[i];
    for (int i = threadIdx.x; i < 128; i += blockDim.x) sWh1[i] = Wh1[i];
    if (threadIdx.x < 16) { sWh2[threadIdx.x] = Wh2[threadIdx.x]; sbu1[threadIdx.x] = bu1[threadIdx.x]; sbh1[threadIdx.x] = bh1[threadIdx.x]; }
    if (threadIdx.x < 8)  sbu2[threadIdx.x] = bu2[threadIdx.x];
    if (threadIdx.x == 0) sbh2 = bh2[0];
    __syncthreads();

    int n = blockIdx.x * blockDim.x + threadIdx.x;
    if (n >= N) return;

    float xv[9];
#pragma unroll
    for (int c = 0; c < 9; c++) xv[c] = g_x[n * 9 + c];

    float ag[32];
    const float4* ar = (const float4*)(g_aggr + (size_t)n * 32);
#pragma unroll
    for (int q = 0; q < 8; q++) {
        float4 t = ar[q];
        ag[4 * q + 0] = t.x; ag[4 * q + 1] = t.y;
        ag[4 * q + 2] = t.z; ag[4 * q + 3] = t.w;
    }

    float u1[16];
#pragma unroll
    for (int i = 0; i < 16; i++) u1[i] = sbu1[i];
#pragma unroll
    for (int c = 0; c < 9; c++) {
        float xc = xv[c];
#pragma unroll
        for (int i = 0; i < 16; i++) u1[i] = fmaf(xc, sWu1[c * 16 + i], u1[i]);
    }
#pragma unroll
    for (int k = 0; k < 32; k++) {
        float gk = ag[k];
#pragma unroll
        for (int i = 0; i < 16; i++) u1[i] = fmaf(gk, sWu1[(9 + k) * 16 + i], u1[i]);
    }
#pragma unroll
    for (int i = 0; i < 16; i++) u1[i] = fmaxf(u1[i], 0.f);

    float u2[8];
#pragma unroll
    for (int j = 0; j < 8; j++) u2[j] = sbu2[j];
#pragma unroll
    for (int i = 0; i < 16; i++) {
        float ui = u1[i];
#pragma unroll
        for (int j = 0; j < 8; j++) u2[j] = fmaf(ui, sWu2[i * 8 + j], u2[j]);
    }
#pragma unroll
    for (int j = 0; j < 8; j++) u2[j] = fmaxf(u2[j], 0.f);

    // h2o: o = relu(u2 @ Wh1 + bh1); z = o . Wh2 + bh2
    float o[16];
#pragma unroll
    for (int i = 0; i < 16; i++) o[i] = sbh1[i];
#pragma unroll
    for (int c = 0; c < 8; c++) {
        float uc = u2[c];
#pragma unroll
        for (int i = 0; i < 16; i++) o[i] = fmaf(uc, sWh1[c * 16 + i], o[i]);
    }
    float z = sbh2;
#pragma unroll
    for (int i = 0; i < 16; i++) z = fmaf(fmaxf(o[i], 0.f), sWh2[i], z);

    out[n] = 1.f / (1.f + __expf(-z));
}

// ---------------------------------------------------------------------------
extern "C" void kernel_launch(void* const* d_in, const int* in_sizes, int n_in,
                              void* d_out, int out_size) {
    const float* x   = (const float*)d_in[0];
    const void*  ei  = d_in[1];
    const float* ea  = (const float*)d_in[2];
    const float* Wm1 = (const float*)d_in[3];
    const float* bm1 = (const float*)d_in[4];
    const float* Wm2 = (const float*)d_in[5];
    const float* bm2 = (const float*)d_in[6];
    const float* Wu1 = (const float*)d_in[7];
    const float* bu1 = (const float*)d_in[8];
    const float* Wu2 = (const float*)d_in[9];
    const float* bu2 = (const float*)d_in[10];
    const float* Wh1 = (const float*)d_in[11];
    const float* bh1 = (const float*)d_in[12];
    const float* Wh2 = (const float*)d_in[13];
    const float* bh2 = (const float*)d_in[14];
    float* out = (float*)d_out;

    int N = in_sizes[0] / 9;
    int E = in_sizes[2];  // edge_attr is [E, 1]

    detect_kernel<<<1, 256>>>((const int*)ei);
    init_kernel<<<(N * 32 + 255) / 256, 256>>>(x, Wm1, bm1, N);
    for (int r = 0; r < 3; r++) {
        edge_kernel<<<(E + 255) / 256, 256>>>(ei, ea, Wm1, bm2, Wm2, E);
        if (r < 2)
            update_kernel<<<(N + 127) / 128, 128>>>(Wu1, bu1, Wu2, bu2, Wm1, bm1, N);
        else
            final_kernel<<<(N + 127) / 128, 128>>>(Wu1, bu1, Wu2, bu2,
                                                   Wh1, bh1, Wh2, bh2, out, N);
    }
}

// round 7
// speedup vs baseline: 1.7481x; 1.7463x over previous
#include <cuda_runtime.h>
#include <cstdint>

// ---------------------------------------------------------------------------
// DistributedMPNN: 3 message-passing rounds (shared weights) + h2o head.
//
//   P[n][32]   = x[n](9) @ Wm1[0:9] + bm1                (per-node hoist of edge layer-1)
//   per edge:  m1 = relu(P[src] + ea*Wm1[9])             (32 FMA)
//              m2 = relu(m1 @ Wm2 + bm2)                 (32x32, fma.rn.f32x2,
//                                                         weights via constant port)
//              aggr[dst] += m2                           (red.global.add.v4.f32)
//   per node:  u1 = relu([x,aggr] @ Wu1 + bu1)  (41x16)
//              u2 = relu(u1 @ Wu2 + bu2)        (16x8)
//              x  = [x0, u2];  P = x @ Wm1 + bm1;  aggr = 0
//   final:     o = relu(u2 @ Wh1 + bh1); out = sigmoid(o @ Wh2 + bh2)
// ---------------------------------------------------------------------------

#define MAXN 50000
#define MAXE 1600000

__device__ float g_P[MAXN * 32];     // per-node layer-1 pre-activation (incl. bm1)
__device__ float g_aggr[MAXN * 32];  // scatter-sum accumulator
__device__ float g_x[MAXN * 9];      // current node features
__device__ int   g_is64;             // edge_index dtype flag

// Edge-MLP weights in constant memory: warp-uniform immediate-offset reads go
// through the uniform constant port (LDCU), off the LSU / smem crossbar.
__constant__ __align__(16) float cW2[1024];  // Wm2 [32][32] row-major
__constant__ __align__(16) float cW9[32];    // Wm1 row 9 (edge_attr weights)
__constant__ __align__(16) float cB2[32];    // bm2

// ---------------------------------------------------------------------------
// Detect edge_index dtype. If int64 (little-endian, values in [0,50000)),
// every odd 32-bit word is 0. For int32 data, 256 consecutive odd-position
// index values being all zero is impossible.
// ---------------------------------------------------------------------------
__global__ void detect_kernel(const int* __restrict__ w) {
    __shared__ int nz;
    if (threadIdx.x == 0) nz = 0;
    __syncthreads();
    if (w[2 * threadIdx.x + 1] != 0) atomicOr(&nz, 1);
    __syncthreads();
    if (threadIdx.x == 0) g_is64 = (nz == 0) ? 1 : 0;
}

// ---------------------------------------------------------------------------
// Init: copy x -> g_x, compute P, zero aggr. One thread per (node, j).
// ---------------------------------------------------------------------------
__global__ void init_kernel(const float* __restrict__ x,
                            const float* __restrict__ Wm1,
                            const float* __restrict__ bm1, int N) {
    int idx = blockIdx.x * blockDim.x + threadIdx.x;
    int n = idx >> 5;
    int j = idx & 31;
    if (n >= N) return;
    float s = bm1[j];
#pragma unroll
    for (int c = 0; c < 9; c++) s = fmaf(x[n * 9 + c], Wm1[c * 32 + j], s);
    g_P[idx] = s;
    g_aggr[idx] = 0.f;
    if (j < 9) g_x[n * 9 + j] = x[n * 9 + j];
}

// ---------------------------------------------------------------------------
// Edge kernel: one thread per edge. Layer-2 with packed f32x2 FMA, weights
// streamed from the constant port. m1 kept packed (u64 pairs) to keep live
// registers under the 83-reg cap (3 CTAs/SM = 24 warps).
// ---------------------------------------------------------------------------
__global__ void __launch_bounds__(256, 3)
edge_kernel(const void* __restrict__ eiv, const float* __restrict__ ea, int E) {
    int e = blockIdx.x * 256 + threadIdx.x;
    if (e >= E) return;

    int src, dst;
    if (g_is64) {
        const long long* ei = (const long long*)eiv;
        src = (int)ei[e];
        dst = (int)ei[(size_t)E + e];
    } else {
        const int* ei = (const int*)eiv;
        src = ei[e];
        dst = ei[(size_t)E + e];
    }
    float a = ea[e];

    // m1 = relu(P[src] + a * W9)   (bm1 already folded into P), packed pairs
    const float4* Pr = (const float4*)(g_P + (size_t)src * 32);
    unsigned long long m1p[16];
#pragma unroll
    for (int q = 0; q < 8; q++) {
        float4 p = Pr[q];
        float4 w9 = *(const float4*)(cW9 + 4 * q);
        float v0 = fmaxf(fmaf(a, w9.x, p.x), 0.f);
        float v1 = fmaxf(fmaf(a, w9.y, p.y), 0.f);
        float v2 = fmaxf(fmaf(a, w9.z, p.z), 0.f);
        float v3 = fmaxf(fmaf(a, w9.w, p.w), 0.f);
        asm("mov.b64 %0, {%1, %2};" : "=l"(m1p[2 * q])     : "f"(v0), "f"(v1));
        asm("mov.b64 %0, {%1, %2};" : "=l"(m1p[2 * q + 1]) : "f"(v2), "f"(v3));
    }

    // acc[j-pair] = bm2, then += m1[k] * Wm2[k][:]
    unsigned long long acc[16];
    {
        const ulonglong2* b2 = (const ulonglong2*)cB2;
#pragma unroll
        for (int q = 0; q < 8; q++) {
            ulonglong2 b = b2[q];
            acc[2 * q] = b.x;
            acc[2 * q + 1] = b.y;
        }
    }

#pragma unroll
    for (int kk = 0; kk < 16; kk++) {
        unsigned r0, r1;
        asm("mov.b64 {%0, %1}, %2;" : "=r"(r0), "=r"(r1) : "l"(m1p[kk]));
        unsigned long long mk0, mk1;
        asm("mov.b64 %0, {%1, %1};" : "=l"(mk0) : "r"(r0));
        asm("mov.b64 %0, {%1, %1};" : "=l"(mk1) : "r"(r1));
        const ulonglong2* w0 = (const ulonglong2*)(cW2 + (2 * kk) * 32);
        const ulonglong2* w1 = (const ulonglong2*)(cW2 + (2 * kk + 1) * 32);
#pragma unroll
        for (int q = 0; q < 8; q++) {
            ulonglong2 wa = w0[q];  // constant-port load, warp-uniform
            asm("fma.rn.f32x2 %0, %1, %2, %0;"
                : "+l"(acc[2 * q]) : "l"(mk0), "l"(wa.x));
            asm("fma.rn.f32x2 %0, %1, %2, %0;"
                : "+l"(acc[2 * q + 1]) : "l"(mk0), "l"(wa.y));
        }
#pragma unroll
        for (int q = 0; q < 8; q++) {
            ulonglong2 wb = w1[q];
            asm("fma.rn.f32x2 %0, %1, %2, %0;"
                : "+l"(acc[2 * q]) : "l"(mk1), "l"(wb.x));
            asm("fma.rn.f32x2 %0, %1, %2, %0;"
                : "+l"(acc[2 * q + 1]) : "l"(mk1), "l"(wb.y));
        }
    }

    // relu + vectorized fire-and-forget scatter-add
    size_t gaddr = __cvta_generic_to_global((void*)(g_aggr + (size_t)dst * 32));
#pragma unroll
    for (int q = 0; q < 8; q++) {
        unsigned r0, r1, r2, r3;
        asm("mov.b64 {%0, %1}, %2;" : "=r"(r0), "=r"(r1) : "l"(acc[2 * q]));
        asm("mov.b64 {%0, %1}, %2;" : "=r"(r2), "=r"(r3) : "l"(acc[2 * q + 1]));
        float v0 = fmaxf(__uint_as_float(r0), 0.f);
        float v1 = fmaxf(__uint_as_float(r1), 0.f);
        float v2 = fmaxf(__uint_as_float(r2), 0.f);
        float v3 = fmaxf(__uint_as_float(r3), 0.f);
        asm volatile("red.global.add.v4.f32 [%0], {%1, %2, %3, %4};"
                     :: "l"((unsigned long long)(gaddr + q * 16)),
                        "f"(v0), "f"(v1), "f"(v2), "f"(v3)
                     : "memory");
    }
}

// ---------------------------------------------------------------------------
// Node update (rounds 0,1): u1/u2 MLP, writes new x, next P, zeroes aggr.
// ---------------------------------------------------------------------------
__global__ void __launch_bounds__(128, 4)
update_kernel(const float* __restrict__ Wu1, const float* __restrict__ bu1,
              const float* __restrict__ Wu2, const float* __restrict__ bu2,
              const float* __restrict__ Wm1, const float* __restrict__ bm1,
              int N) {
    __shared__ float sWu1[656], sWu2[128], sWm1[288];
    __shared__ float sbu1[16], sbu2[8], sbm1[32];
    for (int i = threadIdx.x; i < 656; i += blockDim.x) sWu1[i] = Wu1[i];
    for (int i = threadIdx.x; i < 128; i += blockDim.x) sWu2[i] = Wu2[i];
    for (int i = threadIdx.x; i < 288; i += blockDim.x) sWm1[i] = Wm1[i];
    if (threadIdx.x < 16) sbu1[threadIdx.x] = bu1[threadIdx.x];
    if (threadIdx.x < 8)  sbu2[threadIdx.x] = bu2[threadIdx.x];
    if (threadIdx.x < 32) sbm1[threadIdx.x] = bm1[threadIdx.x];
    __syncthreads();

    int n = blockIdx.x * blockDim.x + threadIdx.x;
    if (n >= N) return;

    float xv[9];
#pragma unroll
    for (int c = 0; c < 9; c++) xv[c] = g_x[n * 9 + c];

    float ag[32];
    float4* ar = (float4*)(g_aggr + (size_t)n * 32);
#pragma unroll
    for (int q = 0; q < 8; q++) {
        float4 t = ar[q];
        ag[4 * q + 0] = t.x; ag[4 * q + 1] = t.y;
        ag[4 * q + 2] = t.z; ag[4 * q + 3] = t.w;
    }

    float u1[16];
#pragma unroll
    for (int i = 0; i < 16; i++) u1[i] = sbu1[i];
#pragma unroll
    for (int c = 0; c < 9; c++) {
        float xc = xv[c];
#pragma unroll
        for (int i = 0; i < 16; i++) u1[i] = fmaf(xc, sWu1[c * 16 + i], u1[i]);
    }
#pragma unroll
    for (int k = 0; k < 32; k++) {
        float gk = ag[k];
#pragma unroll
        for (int i = 0; i < 16; i++) u1[i] = fmaf(gk, sWu1[(9 + k) * 16 + i], u1[i]);
    }
#pragma unroll
    for (int i = 0; i < 16; i++) u1[i] = fmaxf(u1[i], 0.f);

    float u2[8];
#pragma unroll
    for (int j = 0; j < 8; j++) u2[j] = sbu2[j];
#pragma unroll
    for (int i = 0; i < 16; i++) {
        float ui = u1[i];
#pragma unroll
        for (int j = 0; j < 8; j++) u2[j] = fmaf(ui, sWu2[i * 8 + j], u2[j]);
    }
#pragma unroll
    for (int j = 0; j < 8; j++) u2[j] = fmaxf(u2[j], 0.f);

    float nx[9];
    nx[0] = xv[0];
#pragma unroll
    for (int j = 0; j < 8; j++) nx[1 + j] = u2[j];
#pragma unroll
    for (int c = 0; c < 9; c++) g_x[n * 9 + c] = nx[c];

    // next-round P and zero aggr
    float p[32];
#pragma unroll
    for (int j = 0; j < 32; j++) p[j] = sbm1[j];
#pragma unroll
    for (int c = 0; c < 9; c++) {
        float xc = nx[c];
#pragma unroll
        for (int j = 0; j < 32; j++) p[j] = fmaf(xc, sWm1[c * 32 + j], p[j]);
    }
    float4* Pr = (float4*)(g_P + (size_t)n * 32);
    float4 z4 = make_float4(0.f, 0.f, 0.f, 0.f);
#pragma unroll
    for (int q = 0; q < 8; q++) {
        Pr[q] = make_float4(p[4 * q], p[4 * q + 1], p[4 * q + 2], p[4 * q + 3]);
        ar[q] = z4;
    }
}

// ---------------------------------------------------------------------------
// Final round: update MLP fused with h2o head. Writes sigmoid output.
// ---------------------------------------------------------------------------
__global__ void __launch_bounds__(128, 4)
final_kernel(const float* __restrict__ Wu1, const float* __restrict__ bu1,
             const float* __restrict__ Wu2, const float* __restrict__ bu2,
             const float* __restrict__ Wh1, const float* __restrict__ bh1,
             const float* __restrict__ Wh2, const float* __restrict__ bh2,
             float* __restrict__ out, int N) {
    __shared__ float sWu1[656], sWu2[128], sWh1[128], sWh2[16];
    __shared__ float sbu1[16], sbu2[8], sbh1[16], sbh2;
    for (int i = threadIdx.x; i < 656; i += blockDim.x) sWu1[i] = Wu1[i];
    for (int i = threadIdx.x; i < 128; i += blockDim.x) sWu2[i] = Wu2[i];
    for (int i = threadIdx.x; i < 128; i += blockDim.x) sWh1[i] = Wh1[i];
    if (threadIdx.x < 16) { sWh2[threadIdx.x] = Wh2[threadIdx.x]; sbu1[threadIdx.x] = bu1[threadIdx.x]; sbh1[threadIdx.x] = bh1[threadIdx.x]; }
    if (threadIdx.x < 8)  sbu2[threadIdx.x] = bu2[threadIdx.x];
    if (threadIdx.x == 0) sbh2 = bh2[0];
    __syncthreads();

    int n = blockIdx.x * blockDim.x + threadIdx.x;
    if (n >= N) return;

    float xv[9];
#pragma unroll
    for (int c = 0; c < 9; c++) xv[c] = g_x[n * 9 + c];

    float ag[32];
    const float4* ar = (const float4*)(g_aggr + (size_t)n * 32);
#pragma unroll
    for (int q = 0; q < 8; q++) {
        float4 t = ar[q];
        ag[4 * q + 0] = t.x; ag[4 * q + 1] = t.y;
        ag[4 * q + 2] = t.z; ag[4 * q + 3] = t.w;
    }

    float u1[16];
#pragma unroll
    for (int i = 0; i < 16; i++) u1[i] = sbu1[i];
#pragma unroll
    for (int c = 0; c < 9; c++) {
        float xc = xv[c];
#pragma unroll
        for (int i = 0; i < 16; i++) u1[i] = fmaf(xc, sWu1[c * 16 + i], u1[i]);
    }
#pragma unroll
    for (int k = 0; k < 32; k++) {
        float gk = ag[k];
#pragma unroll
        for (int i = 0; i < 16; i++) u1[i] = fmaf(gk, sWu1[(9 + k) * 16 + i], u1[i]);
    }
#pragma unroll
    for (int i = 0; i < 16; i++) u1[i] = fmaxf(u1[i], 0.f);

    float u2[8];
#pragma unroll
    for (int j = 0; j < 8; j++) u2[j] = sbu2[j];
#pragma unroll
    for (int i = 0; i < 16; i++) {
        float ui = u1[i];
#pragma unroll
        for (int j = 0; j < 8; j++) u2[j] = fmaf(ui, sWu2[i * 8 + j], u2[j]);
    }
#pragma unroll
    for (int j = 0; j < 8; j++) u2[j] = fmaxf(u2[j], 0.f);

    // h2o: o = relu(u2 @ Wh1 + bh1); z = o . Wh2 + bh2
    float o[16];
#pragma unroll
    for (int i = 0; i < 16; i++) o[i] = sbh1[i];
#pragma unroll
    for (int c = 0; c < 8; c++) {
        float uc = u2[c];
#pragma unroll
        for (int i = 0; i < 16; i++) o[i] = fmaf(uc, sWh1[c * 16 + i], o[i]);
    }
    float z = sbh2;
#pragma unroll
    for (int i = 0; i < 16; i++) z = fmaf(fmaxf(o[i], 0.f), sWh2[i], z);

    out[n] = 1.f / (1.f + __expf(-z));
}

// ---------------------------------------------------------------------------
extern "C" void kernel_launch(void* const* d_in, const int* in_sizes, int n_in,
                              void* d_out, int out_size) {
    const float* x   = (const float*)d_in[0];
    const void*  ei  = d_in[1];
    const float* ea  = (const float*)d_in[2];
    const float* Wm1 = (const float*)d_in[3];
    const float* bm1 = (const float*)d_in[4];
    const float* Wm2 = (const float*)d_in[5];
    const float* bm2 = (const float*)d_in[6];
    const float* Wu1 = (const float*)d_in[7];
    const float* bu1 = (const float*)d_in[8];
    const float* Wu2 = (const float*)d_in[9];
    const float* bu2 = (const float*)d_in[10];
    const float* Wh1 = (const float*)d_in[11];
    const float* bh1 = (const float*)d_in[12];
    const float* Wh2 = (const float*)d_in[13];
    const float* bh2 = (const float*)d_in[14];
    float* out = (float*)d_out;

    int N = in_sizes[0] / 9;
    int E = in_sizes[2];  // edge_attr is [E, 1]

    // Stage edge-MLP weights into constant memory (D2D, graph-capturable).
    cudaMemcpyToSymbolAsync(cW2, Wm2, 1024 * sizeof(float), 0,
                            cudaMemcpyDeviceToDevice, 0);
    cudaMemcpyToSymbolAsync(cW9, (const char*)Wm1 + 9 * 32 * sizeof(float),
                            32 * sizeof(float), 0, cudaMemcpyDeviceToDevice, 0);
    cudaMemcpyToSymbolAsync(cB2, bm2, 32 * sizeof(float), 0,
                            cudaMemcpyDeviceToDevice, 0);

    detect_kernel<<<1, 256>>>((const int*)ei);
    init_kernel<<<(N * 32 + 255) / 256, 256>>>(x, Wm1, bm1, N);
    for (int r = 0; r < 3; r++) {
        edge_kernel<<<(E + 255) / 256, 256>>>(ei, ea, E);
        if (r < 2)
            update_kernel<<<(N + 127) / 128, 128>>>(Wu1, bu1, Wu2, bu2, Wm1, bm1, N);
        else
            final_kernel<<<(N + 127) / 128, 128>>>(Wu1, bu1, Wu2, bu2,
                                                   Wh1, bh1, Wh2, bh2, out, N);
    }
}

// round 8
// speedup vs baseline: 2.1894x; 1.2525x over previous
#include <cuda_runtime.h>
#include <cstdint>

// ---------------------------------------------------------------------------
// DistributedMPNN: 3 message-passing rounds (shared weights) + h2o head.
//
//   P[n][32]   = x[n](9) @ Wm1[0:9] + bm1            (per-node hoist of edge layer-1)
//   per edge:  m1 = relu(P[src] + ea*Wm1[9])
//              m2 = relu(m1 @ Wm2 + bm2)             (32x32, fma.rn.f32x2, const port)
//              aggr[dst] += m2                       (coalesced red.global.add.v4.f32)
//   per node:  u1 = relu([x,aggr] @ Wu1 + bu1); u2 = relu(u1 @ Wu2 + bu2)
//              x = [x0, u2]; P = x @ Wm1 + bm1; aggr = 0
//   final:     o = relu(u2 @ Wh1 + bh1); out = sigmoid(o @ Wh2 + bh2)
//
// Edge kernel is restructured around L1tex wavefronts: warp-cooperative smem
// staging makes every P-gather and every aggr-scatter touch ONE 128B line per
// edge (was 8+8 lines/edge -> 16 wf/edge -> ~91us/round on the wavefront queue).
// ---------------------------------------------------------------------------

#define MAXN 50000
#define MAXE 1600000

__device__ float g_P[MAXN * 32];     // per-node layer-1 pre-activation (incl. bm1)
__device__ float g_aggr[MAXN * 32];  // scatter-sum accumulator
__device__ float g_x[MAXN * 9];      // current node features
__device__ int   g_is64;             // edge_index dtype flag

__constant__ __align__(16) float cW2[1024];  // Wm2 [32][32] row-major
__constant__ __align__(16) float cW9[32];    // Wm1 row 9 (edge_attr weights)
__constant__ __align__(16) float cB2[32];    // bm2

// ---------------------------------------------------------------------------
// Init: detect edge_index dtype (block 0), copy x -> g_x, compute P, zero aggr.
// One thread per (node, j).
// ---------------------------------------------------------------------------
__global__ void init_kernel(const float* __restrict__ x,
                            const float* __restrict__ Wm1,
                            const float* __restrict__ bm1,
                            const int* __restrict__ eiw, int N) {
    if (blockIdx.x == 0) {
        // int64 little-endian indices < 50000 -> every odd 32-bit word is 0.
        __shared__ int nz;
        if (threadIdx.x == 0) nz = 0;
        __syncthreads();
        if (eiw[2 * threadIdx.x + 1] != 0) atomicOr(&nz, 1);
        __syncthreads();
        if (threadIdx.x == 0) g_is64 = (nz == 0) ? 1 : 0;
    }
    int idx = blockIdx.x * blockDim.x + threadIdx.x;
    int n = idx >> 5;
    int j = idx & 31;
    if (n >= N) return;
    float s = bm1[j];
#pragma unroll
    for (int c = 0; c < 9; c++) s = fmaf(x[n * 9 + c], Wm1[c * 32 + j], s);
    g_P[idx] = s;
    g_aggr[idx] = 0.f;
    if (j < 9) g_x[n * 9 + j] = x[n * 9 + j];
}

// ---------------------------------------------------------------------------
// Edge kernel: each warp owns 32 edges.
//   Phase 1 (coop gather): slot s in 0..31 -> all lanes load P[src_s][lane]
//            (one 128B line per edge) into smem row s.
//   Phase 2 (per-thread GEMV): thread t = edge t; m1 from its smem row,
//            layer-2 via constant-port weights + fma.rn.f32x2.
//   Phase 3 (coop scatter): relu'd m2 rows staged in smem; 8 steps of
//            red.v4 with 8 lanes per destination line (1 line per edge).
// smem rows padded to 36 floats (conflicts <= 4-way on the .128 accesses).
// ---------------------------------------------------------------------------
#define ROWF 36

__global__ void __launch_bounds__(256, 3)
edge_kernel(const void* __restrict__ eiv, const float* __restrict__ ea, int E) {
    __shared__ __align__(16) float sbuf[8][32 * ROWF];
    const unsigned FULL = 0xffffffffu;
    int lane = threadIdx.x & 31;
    int wid = threadIdx.x >> 5;
    float* buf = sbuf[wid];
    long long wbase = ((long long)blockIdx.x * 8 + wid) * 32;
    int e = (int)(wbase + lane);
    bool valid = (wbase + lane) < E;

    int src = 0, dst = 0;
    float a = 0.f;
    if (valid) {
        if (g_is64) {
            const long long* ei = (const long long*)eiv;
            src = (int)ei[e];
            dst = (int)ei[(size_t)E + e];
        } else {
            const int* ei = (const int*)eiv;
            src = ei[e];
            dst = ei[(size_t)E + e];
        }
        a = ea[e];
    }

    // -------- Phase 1: cooperative gather (1 wavefront per edge) --------
#pragma unroll
    for (int s = 0; s < 32; s++) {
        int sS = __shfl_sync(FULL, src, s);
        buf[s * ROWF + lane] = g_P[(size_t)sS * 32 + lane];
    }
    __syncwarp();

    // -------- Phase 2: per-thread GEMV --------
    // m1 = relu(P_row + a * W9), packed into u64 pairs
    unsigned long long m1p[16];
#pragma unroll
    for (int q = 0; q < 8; q++) {
        float4 p = *(const float4*)(buf + lane * ROWF + 4 * q);
        float4 w9 = *(const float4*)(cW9 + 4 * q);
        float v0 = fmaxf(fmaf(a, w9.x, p.x), 0.f);
        float v1 = fmaxf(fmaf(a, w9.y, p.y), 0.f);
        float v2 = fmaxf(fmaf(a, w9.z, p.z), 0.f);
        float v3 = fmaxf(fmaf(a, w9.w, p.w), 0.f);
        asm("mov.b64 %0, {%1, %2};" : "=l"(m1p[2 * q])     : "f"(v0), "f"(v1));
        asm("mov.b64 %0, {%1, %2};" : "=l"(m1p[2 * q + 1]) : "f"(v2), "f"(v3));
    }

    unsigned long long acc[16];
    {
        const ulonglong2* b2 = (const ulonglong2*)cB2;
#pragma unroll
        for (int q = 0; q < 8; q++) {
            ulonglong2 b = b2[q];
            acc[2 * q] = b.x;
            acc[2 * q + 1] = b.y;
        }
    }

#pragma unroll
    for (int kk = 0; kk < 16; kk++) {
        unsigned r0, r1;
        asm("mov.b64 {%0, %1}, %2;" : "=r"(r0), "=r"(r1) : "l"(m1p[kk]));
        unsigned long long mk0, mk1;
        asm("mov.b64 %0, {%1, %1};" : "=l"(mk0) : "r"(r0));
        asm("mov.b64 %0, {%1, %1};" : "=l"(mk1) : "r"(r1));
        const ulonglong2* w0 = (const ulonglong2*)(cW2 + (2 * kk) * 32);
        const ulonglong2* w1 = (const ulonglong2*)(cW2 + (2 * kk + 1) * 32);
#pragma unroll
        for (int q = 0; q < 8; q++) {
            ulonglong2 wa = w0[q];  // constant-port, warp-uniform
            asm("fma.rn.f32x2 %0, %1, %2, %0;"
                : "+l"(acc[2 * q]) : "l"(mk0), "l"(wa.x));
            asm("fma.rn.f32x2 %0, %1, %2, %0;"
                : "+l"(acc[2 * q + 1]) : "l"(mk0), "l"(wa.y));
        }
#pragma unroll
        for (int q = 0; q < 8; q++) {
            ulonglong2 wb = w1[q];
            asm("fma.rn.f32x2 %0, %1, %2, %0;"
                : "+l"(acc[2 * q]) : "l"(mk1), "l"(wb.x));
            asm("fma.rn.f32x2 %0, %1, %2, %0;"
                : "+l"(acc[2 * q + 1]) : "l"(mk1), "l"(wb.y));
        }
    }

    // relu + stage m2 into own smem row (each thread touches only row `lane`)
#pragma unroll
    for (int q = 0; q < 8; q++) {
        unsigned r0, r1, r2, r3;
        asm("mov.b64 {%0, %1}, %2;" : "=r"(r0), "=r"(r1) : "l"(acc[2 * q]));
        asm("mov.b64 {%0, %1}, %2;" : "=r"(r2), "=r"(r3) : "l"(acc[2 * q + 1]));
        float4 v;
        v.x = fmaxf(__uint_as_float(r0), 0.f);
        v.y = fmaxf(__uint_as_float(r1), 0.f);
        v.z = fmaxf(__uint_as_float(r2), 0.f);
        v.w = fmaxf(__uint_as_float(r3), 0.f);
        *(float4*)(buf + lane * ROWF + 4 * q) = v;
    }
    __syncwarp();

    // -------- Phase 3: cooperative scatter (1 wavefront per edge) --------
    int g = lane >> 3;   // group 0..3
    int sub = lane & 7;  // 0..7 -> 16B chunk within the 128B row
#pragma unroll
    for (int i = 0; i < 8; i++) {
        int slot = 4 * i + g;
        int dS = __shfl_sync(FULL, dst, slot);
        bool vS = (wbase + slot) < E;
        float4 v = *(const float4*)(buf + slot * ROWF + 4 * sub);
        if (vS) {
            size_t gaddr = __cvta_generic_to_global(
                (void*)(g_aggr + (size_t)dS * 32 + 4 * sub));
            asm volatile("red.global.add.v4.f32 [%0], {%1, %2, %3, %4};"
                         :: "l"((unsigned long long)gaddr),
                            "f"(v.x), "f"(v.y), "f"(v.z), "f"(v.w)
                         : "memory");
        }
    }
}

// ---------------------------------------------------------------------------
// Node update (rounds 0,1): u1/u2 MLP, writes new x, next P, zeroes aggr.
// ---------------------------------------------------------------------------
__global__ void __launch_bounds__(128, 4)
update_kernel(const float* __restrict__ Wu1, const float* __restrict__ bu1,
              const float* __restrict__ Wu2, const float* __restrict__ bu2,
              const float* __restrict__ Wm1, const float* __restrict__ bm1,
              int N) {
    __shared__ float sWu1[656], sWu2[128], sWm1[288];
    __shared__ float sbu1[16], sbu2[8], sbm1[32];
    for (int i = threadIdx.x; i < 656; i += blockDim.x) sWu1[i] = Wu1[i];
    for (int i = threadIdx.x; i < 128; i += blockDim.x) sWu2[i] = Wu2[i];
    for (int i = threadIdx.x; i < 288; i += blockDim.x) sWm1[i] = Wm1[i];
    if (threadIdx.x < 16) sbu1[threadIdx.x] = bu1[threadIdx.x];
    if (threadIdx.x < 8)  sbu2[threadIdx.x] = bu2[threadIdx.x];
    if (threadIdx.x < 32) sbm1[threadIdx.x] = bm1[threadIdx.x];
    __syncthreads();

    int n = blockIdx.x * blockDim.x + threadIdx.x;
    if (n >= N) return;

    float xv[9];
#pragma unroll
    for (int c = 0; c < 9; c++) xv[c] = g_x[n * 9 + c];

    float ag[32];
    float4* ar = (float4*)(g_aggr + (size_t)n * 32);
#pragma unroll
    for (int q = 0; q < 8; q++) {
        float4 t = ar[q];
        ag[4 * q + 0] = t.x; ag[4 * q + 1] = t.y;
        ag[4 * q + 2] = t.z; ag[4 * q + 3] = t.w;
    }

    float u1[16];
#pragma unroll
    for (int i = 0; i < 16; i++) u1[i] = sbu1[i];
#pragma unroll
    for (int c = 0; c < 9; c++) {
        float xc = xv[c];
#pragma unroll
        for (int i = 0; i < 16; i++) u1[i] = fmaf(xc, sWu1[c * 16 + i], u1[i]);
    }
#pragma unroll
    for (int k = 0; k < 32; k++) {
        float gk = ag[k];
#pragma unroll
        for (int i = 0; i < 16; i++) u1[i] = fmaf(gk, sWu1[(9 + k) * 16 + i], u1[i]);
    }
#pragma unroll
    for (int i = 0; i < 16; i++) u1[i] = fmaxf(u1[i], 0.f);

    float u2[8];
#pragma unroll
    for (int j = 0; j < 8; j++) u2[j] = sbu2[j];
#pragma unroll
    for (int i = 0; i < 16; i++) {
        float ui = u1[i];
#pragma unroll
        for (int j = 0; j < 8; j++) u2[j] = fmaf(ui, sWu2[i * 8 + j], u2[j]);
    }
#pragma unroll
    for (int j = 0; j < 8; j++) u2[j] = fmaxf(u2[j], 0.f);

    float nx[9];
    nx[0] = xv[0];
#pragma unroll
    for (int j = 0; j < 8; j++) nx[1 + j] = u2[j];
#pragma unroll
    for (int c = 0; c < 9; c++) g_x[n * 9 + c] = nx[c];

    float p[32];
#pragma unroll
    for (int j = 0; j < 32; j++) p[j] = sbm1[j];
#pragma unroll
    for (int c = 0; c < 9; c++) {
        float xc = nx[c];
#pragma unroll
        for (int j = 0; j < 32; j++) p[j] = fmaf(xc, sWm1[c * 32 + j], p[j]);
    }
    float4* Pr = (float4*)(g_P + (size_t)n * 32);
    float4 z4 = make_float4(0.f, 0.f, 0.f, 0.f);
#pragma unroll
    for (int q = 0; q < 8; q++) {
        Pr[q] = make_float4(p[4 * q], p[4 * q + 1], p[4 * q + 2], p[4 * q + 3]);
        ar[q] = z4;
    }
}

// ---------------------------------------------------------------------------
// Final round: update MLP fused with h2o head.
// ---------------------------------------------------------------------------
__global__ void __launch_bounds__(128, 4)
final_kernel(const float* __restrict__ Wu1, const float* __restrict__ bu1,
             const float* __restrict__ Wu2, const float* __restrict__ bu2,
             const float* __restrict__ Wh1, const float* __restrict__ bh1,
             const float* __restrict__ Wh2, const float* __restrict__ bh2,
             float* __restrict__ out, int N) {
    __shared__ float sWu1[656], sWu2[128], sWh1[128], sWh2[16];
    __shared__ float sbu1[16], sbu2[8], sbh1[16], sbh2;
    for (int i = threadIdx.x; i < 656; i += blockDim.x) sWu1[i] = Wu1[i];
    for (int i = threadIdx.x; i < 128; i += blockDim.x) sWu2[i] = Wu2[i];
    for (int i = threadIdx.x; i < 128; i += blockDim.x) sWh1[i] = Wh1[i];
    if (threadIdx.x < 16) { sWh2[threadIdx.x] = Wh2[threadIdx.x]; sbu1[threadIdx.x] = bu1[threadIdx.x]; sbh1[threadIdx.x] = bh1[threadIdx.x]; }
    if (threadIdx.x < 8)  sbu2[threadIdx.x] = bu2[threadIdx.x];
    if (threadIdx.x == 0) sbh2 = bh2[0];
    __syncthreads();

    int n = blockIdx.x * blockDim.x + threadIdx.x;
    if (n >= N) return;

    float xv[9];
#pragma unroll
    for (int c = 0; c < 9; c++) xv[c] = g_x[n * 9 + c];

    float ag[32];
    const float4* ar = (const float4*)(g_aggr + (size_t)n * 32);
#pragma unroll
    for (int q = 0; q < 8; q++) {
        float4 t = ar[q];
        ag[4 * q + 0] = t.x; ag[4 * q + 1] = t.y;
        ag[4 * q + 2] = t.z; ag[4 * q + 3] = t.w;
    }

    float u1[16];
#pragma unroll
    for (int i = 0; i < 16; i++) u1[i] = sbu1[i];
#pragma unroll
    for (int c = 0; c < 9; c++) {
        float xc = xv[c];
#pragma unroll
        for (int i = 0; i < 16; i++) u1[i] = fmaf(xc, sWu1[c * 16 + i], u1[i]);
    }
#pragma unroll
    for (int k = 0; k < 32; k++) {
        float gk = ag[k];
#pragma unroll
        for (int i = 0; i < 16; i++) u1[i] = fmaf(gk, sWu1[(9 + k) * 16 + i], u1[i]);
    }
#pragma unroll
    for (int i = 0; i < 16; i++) u1[i] = fmaxf(u1[i], 0.f);

    float u2[8];
#pragma unroll
    for (int j = 0; j < 8; j++) u2[j] = sbu2[j];
#pragma unroll
    for (int i = 0; i < 16; i++) {
        float ui = u1[i];
#pragma unroll
        for (int j = 0; j < 8; j++) u2[j] = fmaf(ui, sWu2[i * 8 + j], u2[j]);
    }
#pragma unroll
    for (int j = 0; j < 8; j++) u2[j] = fmaxf(u2[j], 0.f);

    float o[16];
#pragma unroll
    for (int i = 0; i < 16; i++) o[i] = sbh1[i];
#pragma unroll
    for (int c = 0; c < 8; c++) {
        float uc = u2[c];
#pragma unroll
        for (int i = 0; i < 16; i++) o[i] = fmaf(uc, sWh1[c * 16 + i], o[i]);
    }
    float z = sbh2;
#pragma unroll
    for (int i = 0; i < 16; i++) z = fmaf(fmaxf(o[i], 0.f), sWh2[i], z);

    out[n] = 1.f / (1.f + __expf(-z));
}

// ---------------------------------------------------------------------------
extern "C" void kernel_launch(void* const* d_in, const int* in_sizes, int n_in,
                              void* d_out, int out_size) {
    const float* x   = (const float*)d_in[0];
    const void*  ei  = d_in[1];
    const float* ea  = (const float*)d_in[2];
    const float* Wm1 = (const float*)d_in[3];
    const float* bm1 = (const float*)d_in[4];
    const float* Wm2 = (const float*)d_in[5];
    const float* bm2 = (const float*)d_in[6];
    const float* Wu1 = (const float*)d_in[7];
    const float* bu1 = (const float*)d_in[8];
    const float* Wu2 = (const float*)d_in[9];
    const float* bu2 = (const float*)d_in[10];
    const float* Wh1 = (const float*)d_in[11];
    const float* bh1 = (const float*)d_in[12];
    const float* Wh2 = (const float*)d_in[13];
    const float* bh2 = (const float*)d_in[14];
    float* out = (float*)d_out;

    int N = in_sizes[0] / 9;
    int E = in_sizes[2];  // edge_attr is [E, 1]

    cudaMemcpyToSymbolAsync(cW2, Wm2, 1024 * sizeof(float), 0,
                            cudaMemcpyDeviceToDevice, 0);
    cudaMemcpyToSymbolAsync(cW9, (const char*)Wm1 + 9 * 32 * sizeof(float),
                            32 * sizeof(float), 0, cudaMemcpyDeviceToDevice, 0);
    cudaMemcpyToSymbolAsync(cB2, bm2, 32 * sizeof(float), 0,
                            cudaMemcpyDeviceToDevice, 0);

    init_kernel<<<(N * 32 + 255) / 256, 256>>>(x, Wm1, bm1, (const int*)ei, N);
    for (int r = 0; r < 3; r++) {
        edge_kernel<<<(E + 255) / 256, 256>>>(ei, ea, E);
        if (r < 2)
            update_kernel<<<(N + 127) / 128, 128>>>(Wu1, bu1, Wu2, bu2, Wm1, bm1, N);
        else
            final_kernel<<<(N + 127) / 128, 128>>>(Wu1, bu1, Wu2, bu2,
                                                   Wh1, bh1, Wh2, bh2, out, N);
    }
}